// round 6
// baseline (speedup 1.0000x reference)
#include <cuda_runtime.h>
#include <cuda_bf16.h>
#include <math.h>
#include <stdint.h>

// Problem constants
#define TX 64
#define BB 64
#define TY 32
#define EE 256
#define HH 512
#define H3 1536
#define KY 32000
#define CTXD 1024      // 2H
#define RNNIN 1280     // E + 2H
#define NTILE (KY / 256)   // 125 vocab tiles

// ---------------- device scratch ----------------
__device__ float g_gi_f[TX * BB * H3];
__device__ float g_gi_b[TX * BB * H3];
__device__ float g_henc[2][2][BB * HH];
__device__ float g_enc[TX * BB * CTXD];
__device__ float g_P[TX * BB * HH];
__device__ float g_hd[2][BB * HH];
__device__ float g_q[BB * HH];
__device__ float g_rnnin[BB * RNNIN];
__device__ int   g_tok[BB];
__device__ float g_lse[TY * BB];

__device__ __nv_bfloat16 g_wh[(size_t)KY * H3];
__device__ __nv_bfloat16 g_wl[(size_t)KY * H3];
__device__ __nv_bfloat16 g_ah[BB * H3];
__device__ __nv_bfloat16 g_al[BB * H3];

__device__ float g_pm[NTILE][BB];
__device__ int   g_pa[NTILE][BB];
__device__ float g_ps[NTILE][BB];
__device__ unsigned g_cnt;

__device__ volatile unsigned g_bar_gen[2];
__device__ unsigned g_bar_cnt[2];

__device__ __forceinline__ float sigm(float x) { return 1.0f / (1.0f + expf(-x)); }

__device__ __forceinline__ void split_store(float v, __nv_bfloat16* ph, __nv_bfloat16* pl)
{
    __nv_bfloat16 h = __float2bfloat16(v);
    *ph = h;
    *pl = __float2bfloat16(v - __bfloat162float(h));
}

__device__ __forceinline__ uint32_t smem_u32(const void* p) {
    uint32_t a;
    asm("{ .reg .u64 t; cvta.to.shared.u64 t, %1; cvt.u32.u64 %0, t; }" : "=r"(a) : "l"(p));
    return a;
}

#define MBAR_INIT(mbar, count) \
    asm volatile("mbarrier.init.shared.b64 [%0], %1;" :: "r"(mbar), "r"((uint32_t)(count)) : "memory")

#define MBAR_WAIT_PARITY(mbar, par) do { \
    uint32_t _m = (mbar), _p = (par), _d; \
    asm volatile("{\n\t.reg .pred p;\n\t" \
        "mbarrier.try_wait.parity.acquire.cta.shared::cta.b64 p, [%1], %2;\n\t" \
        "selp.b32 %0, 1, 0, p;\n\t}" : "=r"(_d) : "r"(_m), "r"(_p) : "memory"); \
    if (!_d) { \
        asm volatile("{\n\t.reg .pred P1;\n\t" \
            "WL_%=:\n\t" \
            "mbarrier.try_wait.parity.acquire.cta.shared::cta.b64 P1, [%0], %1, 0x989680;\n\t" \
            "@P1 bra.uni WD_%=;\n\t" \
            "bra.uni WL_%=;\n\t" \
            "WD_%=:\n\t}" :: "r"(_m), "r"(_p) : "memory"); \
    } \
} while (0)

__device__ __forceinline__ void bulk128(uint32_t dst, const void* src, uint32_t mbar)
{
    asm volatile(
        "cp.async.bulk.shared::cluster.global.mbarrier::complete_tx::bytes [%0], [%1], 128, [%2];"
        :: "r"(dst), "l"(src), "r"(mbar) : "memory");
}

// ---------------- init ----------------
__global__ void init_kernel() {
    int i = blockIdx.x * blockDim.x + threadIdx.x;
    if (i < BB * HH) {
        g_henc[0][0][i] = 0.f;
        g_henc[1][0][i] = 0.f;
    }
    if (i < BB) g_tok[i] = 1;
    if (i < 2) { g_bar_gen[i] = 0; g_bar_cnt[i] = 0; }
    if (i == 0) g_cnt = 0;
}

// ---------------- W_lsm -> bf16 hi/lo split ----------------
__global__ __launch_bounds__(256) void convw_kernel(const float* __restrict__ W) {
    size_t i = (size_t)blockIdx.x * blockDim.x + threadIdx.x;
    const float4* W4 = (const float4*)W;
    float4 v = W4[i];
    __nv_bfloat16 h0 = __float2bfloat16(v.x);
    __nv_bfloat16 h1 = __float2bfloat16(v.y);
    __nv_bfloat16 h2 = __float2bfloat16(v.z);
    __nv_bfloat16 h3 = __float2bfloat16(v.w);
    __nv_bfloat16 l0 = __float2bfloat16(v.x - __bfloat162float(h0));
    __nv_bfloat16 l1 = __float2bfloat16(v.y - __bfloat162float(h1));
    __nv_bfloat16 l2 = __float2bfloat16(v.z - __bfloat162float(h2));
    __nv_bfloat16 l3 = __float2bfloat16(v.w - __bfloat162float(h3));
    __nv_bfloat162* H2 = reinterpret_cast<__nv_bfloat162*>(g_wh);
    __nv_bfloat162* L2 = reinterpret_cast<__nv_bfloat162*>(g_wl);
    H2[2 * i]     = __nv_bfloat162{h0, h1};
    H2[2 * i + 1] = __nv_bfloat162{h2, h3};
    L2[2 * i]     = __nv_bfloat162{l0, l1};
    L2[2 * i + 1] = __nv_bfloat162{l2, l3};
}

// ---------------- mma.sync bf16 helper ----------------
__device__ __forceinline__ void mma16816(float* d, const uint32_t* a, uint32_t b0, uint32_t b1)
{
    asm volatile(
        "mma.sync.aligned.m16n8k16.row.col.f32.bf16.bf16.f32 "
        "{%0,%1,%2,%3}, {%4,%5,%6,%7}, {%8,%9}, {%0,%1,%2,%3};"
        : "+f"(d[0]), "+f"(d[1]), "+f"(d[2]), "+f"(d[3])
        : "r"(a[0]), "r"(a[1]), "r"(a[2]), "r"(a[3]), "r"(b0), "r"(b1));
}

// ---------------- logits GEMM (split bf16) with bulk-async loads ----------------
#define LG_KC 64
#define LG_ROWB 144
#define LG_W_BYTES (256 * LG_ROWB)                   // 36864
#define LG_A_BYTES (64 * LG_ROWB)                    // 9216
#define LG_STAGE (2 * LG_W_BYTES + 2 * LG_A_BYTES)   // 92160
#define LG_CHUNK_TX 81920                            // 640 rows x 128B
#define LG_SMEM_TOTAL (1024 + 2 * LG_STAGE)          // 185344

__global__ __launch_bounds__(256, 1) void logits_mma_kernel(
    const float* __restrict__ b_lsm, float* __restrict__ out, int step)
{
    extern __shared__ char smem[];
    __shared__ int s_last;
    int tid = threadIdx.x;
    int wid = tid >> 5, lane = tid & 31;
    int vb = blockIdx.x * 256;
    uint32_t sb = smem_u32(smem);

    if (tid == 0) {
        MBAR_INIT(sb + 0, 256);
        MBAR_INIT(sb + 8, 256);
    }
    __syncthreads();

    // each thread arrives with its own expected bytes, then issues its own copies
    auto issue_chunk = [&](int kc, int buf) {
        uint32_t mbar = sb + 8u * buf;
        uint32_t stage = sb + 1024u + buf * LG_STAGE;
        uint32_t mybytes = 256u + (tid < 128 ? 128u : 0u);
        asm volatile("mbarrier.arrive.expect_tx.shared.b64 _, [%0], %1;"
                     :: "r"(mbar), "r"(mybytes) : "memory");
        const __nv_bfloat16* swh = g_wh + (size_t)(vb + tid) * H3 + kc * LG_KC;
        bulk128(stage + tid * LG_ROWB, swh, mbar);
        const __nv_bfloat16* swl = g_wl + (size_t)(vb + tid) * H3 + kc * LG_KC;
        bulk128(stage + LG_W_BYTES + tid * LG_ROWB, swl, mbar);
        if (tid < 64) {
            bulk128(stage + 2 * LG_W_BYTES + tid * LG_ROWB,
                    g_ah + (size_t)tid * H3 + kc * LG_KC, mbar);
        } else if (tid < 128) {
            int r = tid - 64;
            bulk128(stage + 2 * LG_W_BYTES + LG_A_BYTES + r * LG_ROWB,
                    g_al + (size_t)r * H3 + kc * LG_KC, mbar);
        }
    };

    float acc[2][8][4];
#pragma unroll
    for (int mt = 0; mt < 2; mt++)
#pragma unroll
        for (int nt = 0; nt < 8; nt++)
#pragma unroll
            for (int i = 0; i < 4; i++) acc[mt][nt][i] = 0.f;

    int m0 = wid * 32;
    int krow = lane >> 2;
    int kcol4 = (lane & 3) * 4;

    issue_chunk(0, 0);
    issue_chunk(1, 1);

    for (int c = 0; c < H3 / LG_KC; c++) {
        int buf = c & 1;
        MBAR_WAIT_PARITY(sb + 8u * buf, (c >> 1) & 1);

        char* base = smem + 1024 + buf * LG_STAGE;
        const char* wh = base;
        const char* wl = base + LG_W_BYTES;
        const char* ab_h = base + 2 * LG_W_BYTES;
        const char* ab_l = ab_h + LG_A_BYTES;

#pragma unroll
        for (int kt = 0; kt < 4; kt++) {
            int kb = kt * 32 + kcol4;
            uint32_t ah[2][4], al[2][4];
#pragma unroll
            for (int mt = 0; mt < 2; mt++) {
                int ro = (m0 + mt * 16 + krow) * LG_ROWB + kb;
                ah[mt][0] = *(const uint32_t*)(wh + ro);
                ah[mt][1] = *(const uint32_t*)(wh + ro + 8 * LG_ROWB);
                ah[mt][2] = *(const uint32_t*)(wh + ro + 16);
                ah[mt][3] = *(const uint32_t*)(wh + ro + 8 * LG_ROWB + 16);
                al[mt][0] = *(const uint32_t*)(wl + ro);
                al[mt][1] = *(const uint32_t*)(wl + ro + 8 * LG_ROWB);
                al[mt][2] = *(const uint32_t*)(wl + ro + 16);
                al[mt][3] = *(const uint32_t*)(wl + ro + 8 * LG_ROWB + 16);
            }
#pragma unroll
            for (int nt = 0; nt < 8; nt++) {
                int rb = (nt * 8 + krow) * LG_ROWB + kb;
                uint32_t bh0 = *(const uint32_t*)(ab_h + rb);
                uint32_t bh1 = *(const uint32_t*)(ab_h + rb + 16);
                uint32_t bl0 = *(const uint32_t*)(ab_l + rb);
                uint32_t bl1 = *(const uint32_t*)(ab_l + rb + 16);
#pragma unroll
                for (int mt = 0; mt < 2; mt++) {
                    mma16816(acc[mt][nt], ah[mt], bh0, bh1);
                    mma16816(acc[mt][nt], ah[mt], bl0, bl1);
                    mma16816(acc[mt][nt], al[mt], bh0, bh1);
                }
            }
        }
        __syncthreads();   // all readers done with this buffer
        if (c + 2 < H3 / LG_KC) issue_chunk(c + 2, buf);
    }

    // ---- epilogue: bias + store ----
    float* obase = out + (size_t)step * BB * KY;
#pragma unroll
    for (int mt = 0; mt < 2; mt++) {
#pragma unroll
        for (int h = 0; h < 2; h++) {
            int v = vb + m0 + mt * 16 + krow + h * 8;
            float bias = b_lsm[v];
#pragma unroll
            for (int nt = 0; nt < 8; nt++) {
                int b0 = nt * 8 + (lane & 3) * 2;
                acc[mt][nt][h * 2 + 0] += bias;
                acc[mt][nt][h * 2 + 1] += bias;
                obase[(size_t)b0 * KY + v]       = acc[mt][nt][h * 2 + 0];
                obase[(size_t)(b0 + 1) * KY + v] = acc[mt][nt][h * 2 + 1];
            }
        }
    }
    __syncthreads();  // buffers done; reuse smem for reductions

    float* smf  = (float*)smem;            // [8][64]
    int*   smi  = (int*)(smem + 2048);     // [8][64]
    float* tmx  = (float*)(smem + 4096);   // [64]
    int*   targ = (int*)(smem + 4352);     // [64]

    int vbase = vb + m0 + krow;
    // phase 1: max + argmax
#pragma unroll
    for (int nt = 0; nt < 8; nt++) {
#pragma unroll
        for (int c = 0; c < 2; c++) {
            int bcol = nt * 8 + (lane & 3) * 2 + c;
            float mv = acc[0][nt][c];     int mi = vbase;
            float v2 = acc[0][nt][2 + c];
            if (v2 > mv) { mv = v2; mi = vbase + 8; }
            v2 = acc[1][nt][c];
            if (v2 > mv) { mv = v2; mi = vbase + 16; }
            v2 = acc[1][nt][2 + c];
            if (v2 > mv) { mv = v2; mi = vbase + 24; }
#pragma unroll
            for (int o = 4; o <= 16; o <<= 1) {
                float ov = __shfl_xor_sync(0xffffffffu, mv, o);
                int oi = __shfl_xor_sync(0xffffffffu, mi, o);
                if (ov > mv || (ov == mv && oi < mi)) { mv = ov; mi = oi; }
            }
            if ((lane >> 2) == 0) { smf[wid * 64 + bcol] = mv; smi[wid * 64 + bcol] = mi; }
        }
    }
    __syncthreads();
    if (tid < 64) {
        float mv = smf[tid]; int mi = smi[tid];
#pragma unroll
        for (int w = 1; w < 8; w++) {
            float ov = smf[w * 64 + tid]; int oi = smi[w * 64 + tid];
            if (ov > mv || (ov == mv && oi < mi)) { mv = ov; mi = oi; }
        }
        tmx[tid] = mv; targ[tid] = mi;
    }
    __syncthreads();
    // phase 2: sum of exp(x - tile_max)
#pragma unroll
    for (int nt = 0; nt < 8; nt++) {
#pragma unroll
        for (int c = 0; c < 2; c++) {
            int bcol = nt * 8 + (lane & 3) * 2 + c;
            float tm = tmx[bcol];
            float s = expf(acc[0][nt][c] - tm) + expf(acc[0][nt][2 + c] - tm)
                    + expf(acc[1][nt][c] - tm) + expf(acc[1][nt][2 + c] - tm);
#pragma unroll
            for (int o = 4; o <= 16; o <<= 1)
                s += __shfl_xor_sync(0xffffffffu, s, o);
            if ((lane >> 2) == 0) smf[wid * 64 + bcol] = s;
        }
    }
    __syncthreads();
    if (tid < 64) {
        float s = 0.f;
#pragma unroll
        for (int w = 0; w < 8; w++) s += smf[w * 64 + tid];
        g_pm[blockIdx.x][tid] = tmx[tid];
        g_pa[blockIdx.x][tid] = targ[tid];
        g_ps[blockIdx.x][tid] = s;
        __threadfence();
    }
    __syncthreads();

    // ---- ticket: last CTA merges partials -> g_tok, g_lse ----
    if (tid == 0) {
        unsigned t = atomicAdd(&g_cnt, 1u);
        s_last = (t == NTILE - 1u) ? 1 : 0;
    }
    __syncthreads();
    if (s_last) {
        __threadfence();
        float* rm = (float*)smem;            // [4][64]
        float* rs = (float*)(smem + 2048);
        int*   ra = (int*)(smem + 4096);
        float* rmax = (float*)(smem + 6144);
        int b = tid & 63;
        int grp = tid >> 6;   // 0..3
        float maxv = -1e30f; int argi = 0x7fffffff;
        float mv = -1e30f, sv = 0.f;
        for (int t = grp; t < NTILE; t += 4) {
            float m = g_pm[t][b];
            float s = g_ps[t][b];
            int a = g_pa[t][b];
            if (m > maxv || (m == maxv && a < argi)) { maxv = m; argi = a; }
            if (m > mv) { sv = sv * expf(mv - m) + s; mv = m; }
            else sv += s * expf(m - mv);
        }
        rm[grp * 64 + b] = mv;
        rs[grp * 64 + b] = sv;
        ra[grp * 64 + b] = argi;
        rmax[grp * 64 + b] = maxv;
        __syncthreads();
        if (tid < 64) {
            float M = rm[tid]; float S = rs[tid];
            float bmax = rmax[tid]; int barg = ra[tid];
#pragma unroll
            for (int g2 = 1; g2 < 4; g2++) {
                float m = rm[g2 * 64 + tid];
                float s = rs[g2 * 64 + tid];
                if (m > M) { S = S * expf(M - m) + s; M = m; }
                else S += s * expf(m - M);
                float bm = rmax[g2 * 64 + tid]; int ba = ra[g2 * 64 + tid];
                if (bm > bmax || (bm == bmax && ba < barg)) { bmax = bm; barg = ba; }
            }
            g_tok[tid] = barg;
            g_lse[step * BB + tid] = M + logf(S);
        }
        if (tid == 0) g_cnt = 0;
    }
}

// ---------------- log-softmax normalize ----------------
__global__ __launch_bounds__(256) void lsm_norm_kernel(float* __restrict__ out, int step)
{
    int idx = blockIdx.x * 256 + threadIdx.x;    // over BB*KY/4
    int b = idx / (KY / 4);
    float lse = g_lse[step * BB + b];
    float4* o = (float4*)(out + (size_t)step * BB * KY);
    float4 v = o[idx];
    v.x -= lse; v.y -= lse; v.z -= lse; v.w -= lse;
    o[idx] = v;
}

// ---------------- generic SGEMM ----------------
__global__ __launch_bounds__(256) void sgemm_kernel(
    const float* __restrict__ A, const int* __restrict__ gather,
    const float* __restrict__ W, int ldw,
    const float* __restrict__ bias,
    float* __restrict__ C, int N, int K)
{
    __shared__ float As[16][64];
    __shared__ float Ws[16][128];
    int tid = threadIdx.x;
    int m0 = blockIdx.y * 64;
    int n0 = blockIdx.x * 128;
    int tx = tid & 15, ty = tid >> 4;

    float acc[4][8];
#pragma unroll
    for (int i = 0; i < 4; i++)
#pragma unroll
        for (int j = 0; j < 8; j++) acc[i][j] = 0.f;

    int lrow = tid >> 2;
    int lk = (tid & 3) * 4;
    int arow = m0 + lrow;
    int aphys = gather ? gather[arow] : arow;
    const float* Aptr = A + (size_t)aphys * K + lk;

    for (int k0 = 0; k0 < K; k0 += 16) {
        float4 av = *(const float4*)(Aptr + k0);
        As[lk + 0][lrow] = av.x; As[lk + 1][lrow] = av.y;
        As[lk + 2][lrow] = av.z; As[lk + 3][lrow] = av.w;
#pragma unroll
        for (int r = 0; r < 2; r++) {
            int nrow = lrow + r * 64;
            float4 wv = *(const float4*)(W + (size_t)(n0 + nrow) * ldw + k0 + lk);
            Ws[lk + 0][nrow] = wv.x; Ws[lk + 1][nrow] = wv.y;
            Ws[lk + 2][nrow] = wv.z; Ws[lk + 3][nrow] = wv.w;
        }
        __syncthreads();
#pragma unroll
        for (int kk = 0; kk < 16; kk++) {
            float a[4];
#pragma unroll
            for (int i = 0; i < 4; i++) a[i] = As[kk][ty * 4 + i];
            float4 b0 = *(const float4*)&Ws[kk][tx * 8];
            float4 b1 = *(const float4*)&Ws[kk][tx * 8 + 4];
            float bb8[8] = { b0.x, b0.y, b0.z, b0.w, b1.x, b1.y, b1.z, b1.w };
#pragma unroll
            for (int i = 0; i < 4; i++)
#pragma unroll
                for (int j = 0; j < 8; j++) acc[i][j] += a[i] * bb8[j];
        }
        __syncthreads();
    }
#pragma unroll
    for (int i = 0; i < 4; i++) {
        int m = m0 + ty * 4 + i;
        float* crow = C + (size_t)m * N + n0 + tx * 8;
#pragma unroll
        for (int j = 0; j < 8; j++) {
            float v = acc[i][j];
            if (bias) v += bias[n0 + tx * 8 + j];
            crow[j] = v;
        }
    }
}

// ---------------- persistent encoder ----------------
#define ENC_WS_FLOATS (24 * 512)
#define ENC_SMEM ((ENC_WS_FLOATS + 128 * 65) * 4)

__device__ __forceinline__ void dir_barrier(int dir, int tid)
{
    __threadfence();
    __syncthreads();
    if (tid == 0) {
        unsigned gen = g_bar_gen[dir];
        unsigned t = atomicAdd(&g_bar_cnt[dir], 1u);
        if (t == 63u) {
            g_bar_cnt[dir] = 0u;
            __threadfence();
            g_bar_gen[dir] = gen + 1u;
        } else {
            while (g_bar_gen[dir] == gen) __nanosleep(40);
        }
    }
    __syncthreads();
}

__global__ __launch_bounds__(512, 1) void enc_persist_kernel(
    const float* __restrict__ Whh_f, const float* __restrict__ bhh_f,
    const float* __restrict__ Whh_b, const float* __restrict__ bhh_b)
{
    extern __shared__ float sm[];
    float* ws = sm;
    float (*hs)[65] = (float(*)[65])(sm + ENC_WS_FLOATS);

    int dir = blockIdx.y;
    const float* Whh = dir ? Whh_b : Whh_f;
    const float* bhh = dir ? bhh_b : bhh_f;
    int tid = threadIdx.x;
    int b = tid & 63;
    int jl = tid >> 6;
    int j0 = blockIdx.x * 8;
    int j = j0 + jl;
    int colofs = dir ? HH : 0;

    for (int idx = tid; idx < ENC_WS_FLOATS; idx += 512) {
        int rr = idx >> 9, kk = idx & 511;
        ws[idx] = Whh[(size_t)((rr >> 3) * HH + j0 + (rr & 7)) * HH + kk];
    }
    float br = bhh[j], bz = bhh[HH + j], bn = bhh[2 * HH + j];
    __syncthreads();

    for (int t = 0; t < TX; t++) {
        int par = t & 1;
        int row = dir ? (TX - 1 - t) : t;
        const float* gi = (dir ? g_gi_b : g_gi_f) + (size_t)row * BB * H3;
        const float* hin = g_henc[dir][par];
        float* hout = g_henc[dir][par ^ 1];

        float dr = 0.f, dz = 0.f, dn = 0.f;
        for (int kb = 0; kb < 4; kb++) {
            int kbase = kb * 128;
#pragma unroll
            for (int r = 0; r < 16; r++) {
                int i = tid + r * 512;
                int kk = i & 127, bb2 = i >> 7;
                hs[kk][bb2] = __ldcg(&hin[bb2 * HH + kbase + kk]);
            }
            __syncthreads();
            const float* wr4 = ws + jl * 512 + kbase;
            const float* wz4 = ws + (8 + jl) * 512 + kbase;
            const float* wn4 = ws + (16 + jl) * 512 + kbase;
#pragma unroll 8
            for (int k = 0; k < 128; k += 4) {
                float4 wr = *(const float4*)(wr4 + k);
                float4 wz = *(const float4*)(wz4 + k);
                float4 wn = *(const float4*)(wn4 + k);
                float h0 = hs[k][b], h1 = hs[k + 1][b], h2v = hs[k + 2][b], h3v = hs[k + 3][b];
                dr += h0 * wr.x + h1 * wr.y + h2v * wr.z + h3v * wr.w;
                dz += h0 * wz.x + h1 * wz.y + h2v * wz.z + h3v * wz.w;
                dn += h0 * wn.x + h1 * wn.y + h2v * wn.z + h3v * wn.w;
            }
            __syncthreads();
        }

        const float* girow = gi + b * H3;
        float r = sigm(girow[j] + dr + br);
        float z = sigm(girow[HH + j] + dz + bz);
        float n = tanhf(girow[2 * HH + j] + r * (dn + bn));
        float hold = __ldcg(&hin[b * HH + j]);
        float h2 = (1.f - z) * n + z * hold;
        __stcg(&hout[b * HH + j], h2);
        g_enc[(size_t)(row * BB + b) * CTXD + colofs + j] = h2;

        if (t + 1 < TX) dir_barrier(dir, tid);
    }
}

// ---------------- column projection ----------------
__global__ __launch_bounds__(512) void colproj_kernel(
    const float* __restrict__ src, const float* __restrict__ W, int ldw,
    const float* __restrict__ bias, float* __restrict__ dst, int act)
{
    __shared__ float hs[128][65];
    __shared__ float ws[8][128];
    int tid = threadIdx.x;
    int b = tid & 63;
    int jl = tid >> 6;
    int j0 = blockIdx.x * 8;
    int j = j0 + jl;

    float acc = 0.f;
    for (int kb = 0; kb < 4; kb++) {
        int kbase = kb * 128;
#pragma unroll
        for (int r = 0; r < 16; r++) {
            int i = tid + r * 512;
            int kk = i & 127, bb2 = i >> 7;
            hs[kk][bb2] = src[bb2 * HH + kbase + kk];
        }
#pragma unroll
        for (int r = 0; r < 2; r++) {
            int i = tid + r * 512;
            int kk = i & 127, rr = i >> 7;
            ws[rr][kk] = W[(size_t)(j0 + rr) * ldw + kbase + kk];
        }
        __syncthreads();
#pragma unroll 8
        for (int k = 0; k < 128; k += 4) {
            float4 wv = *(const float4*)&ws[jl][k];
            acc += hs[k][b] * wv.x + hs[k + 1][b] * wv.y
                 + hs[k + 2][b] * wv.z + hs[k + 3][b] * wv.w;
        }
        __syncthreads();
    }
    if (bias) acc += bias[j];
    if (act) acc = tanhf(acc);
    dst[b * HH + j] = acc;
}

// ---------------- attention + embedding (fused) ----------------
__global__ __launch_bounds__(256) void attn_kernel(
    const float* __restrict__ W_a2, const float* __restrict__ b_a2,
    const float* __restrict__ dec_emb)
{
    __shared__ float qs[HH];
    __shared__ float was[HH];
    __shared__ float ss[TX];
    __shared__ float wgt[TX];

    int b = blockIdx.x;
    int tid = threadIdx.x;
    int lane = tid & 31;
    int warp = tid >> 5;

    int tok = g_tok[b];
    for (int i = tid; i < EE; i += 256)
        g_rnnin[b * RNNIN + i] = dec_emb[(size_t)tok * EE + i];

    for (int i = tid; i < HH; i += 256) {
        qs[i] = g_q[b * HH + i];
        was[i] = W_a2[i];
    }
    __syncthreads();

    for (int tt = 0; tt < 8; tt++) {
        int t = warp * 8 + tt;
        const float* Prow = g_P + (size_t)(t * BB + b) * HH;
        float p = 0.f;
#pragma unroll 4
        for (int jj = lane; jj < HH; jj += 32)
            p += was[jj] * tanhf(qs[jj] + Prow[jj]);
#pragma unroll
        for (int o = 16; o > 0; o >>= 1)
            p += __shfl_down_sync(0xffffffffu, p, o);
        if (lane == 0) ss[t] = p + b_a2[0];
    }
    __syncthreads();

    if (tid < 32) {
        float v0 = ss[tid], v1 = ss[tid + 32];
        float m = fmaxf(v0, v1);
#pragma unroll
        for (int o = 16; o > 0; o >>= 1)
            m = fmaxf(m, __shfl_xor_sync(0xffffffffu, m, o));
        float e0 = expf(v0 - m), e1 = expf(v1 - m);
        float s = e0 + e1;
#pragma unroll
        for (int o = 16; o > 0; o >>= 1)
            s += __shfl_xor_sync(0xffffffffu, s, o);
        wgt[tid] = e0 / s;
        wgt[tid + 32] = e1 / s;
    }
    __syncthreads();

    for (int i = tid; i < CTXD; i += 256) {
        float c = 0.f;
#pragma unroll 8
        for (int t = 0; t < TX; t++)
            c += wgt[t] * g_enc[(size_t)(t * BB + b) * CTXD + i];
        g_rnnin[b * RNNIN + EE + i] = c;
        split_store(c, &g_ah[b * H3 + HH + i], &g_al[b * H3 + HH + i]);
    }
}

// ---------------- decoder GRU ----------------
__global__ __launch_bounds__(256) void decgru_kernel(
    int s,
    const float* __restrict__ Wih, const float* __restrict__ Whh,
    const float* __restrict__ bih, const float* __restrict__ bhh)
{
    __shared__ float xs[128][65];
    __shared__ float ws[12][128];

    int tid = threadIdx.x;
    int b = tid & 63;
    int jl = tid >> 6;
    int j0 = blockIdx.x * 4;
    int j = j0 + jl;
    int par = s & 1;
    const float* hin = g_hd[par];
    float* hout = g_hd[par ^ 1];

    float ar = 0.f, az = 0.f, anx = 0.f, anh = 0.f;

    for (int kb = 0; kb < 10; kb++) {
        int kbase = kb * 128;
#pragma unroll
        for (int r = 0; r < 32; r++) {
            int i = tid + r * 256;
            int kk = i & 127, bb2 = i >> 7;
            xs[kk][bb2] = g_rnnin[bb2 * RNNIN + kbase + kk];
        }
#pragma unroll
        for (int r = 0; r < 6; r++) {
            int i = tid + r * 256;
            int kk = i & 127, rr = i >> 7;
            int g = rr >> 2, jloc = rr & 3;
            ws[rr][kk] = Wih[(size_t)(g * HH + j0 + jloc) * RNNIN + kbase + kk];
        }
        __syncthreads();
#pragma unroll 8
        for (int k = 0; k < 128; k += 4) {
            float4 wr = *(const float4*)&ws[jl][k];
            float4 wz = *(const float4*)&ws[4 + jl][k];
            float4 wn = *(const float4*)&ws[8 + jl][k];
            float x0 = xs[k][b], x1 = xs[k + 1][b], x2 = xs[k + 2][b], x3 = xs[k + 3][b];
            ar += x0 * wr.x + x1 * wr.y + x2 * wr.z + x3 * wr.w;
            az += x0 * wz.x + x1 * wz.y + x2 * wz.z + x3 * wz.w;
            anx += x0 * wn.x + x1 * wn.y + x2 * wn.z + x3 * wn.w;
        }
        __syncthreads();
    }

    for (int kb = 0; kb < 4; kb++) {
        int kbase = kb * 128;
#pragma unroll
        for (int r = 0; r < 32; r++) {
            int i = tid + r * 256;
            int kk = i & 127, bb2 = i >> 7;
            xs[kk][bb2] = hin[bb2 * HH + kbase + kk];
        }
#pragma unroll
        for (int r = 0; r < 6; r++) {
            int i = tid + r * 256;
            int kk = i & 127, rr = i >> 7;
            int g = rr >> 2, jloc = rr & 3;
            ws[rr][kk] = Whh[(size_t)(g * HH + j0 + jloc) * HH + kbase + kk];
        }
        __syncthreads();
#pragma unroll 8
        for (int k = 0; k < 128; k += 4) {
            float4 wr = *(const float4*)&ws[jl][k];
            float4 wz = *(const float4*)&ws[4 + jl][k];
            float4 wn = *(const float4*)&ws[8 + jl][k];
            float x0 = xs[k][b], x1 = xs[k + 1][b], x2 = xs[k + 2][b], x3 = xs[k + 3][b];
            ar += x0 * wr.x + x1 * wr.y + x2 * wr.z + x3 * wr.w;
            az += x0 * wz.x + x1 * wz.y + x2 * wz.z + x3 * wz.w;
            anh += x0 * wn.x + x1 * wn.y + x2 * wn.z + x3 * wn.w;
        }
        __syncthreads();
    }

    float r = sigm(ar + bih[j] + bhh[j]);
    float z = sigm(az + bih[HH + j] + bhh[HH + j]);
    float n = tanhf(anx + bih[2 * HH + j] + r * (anh + bhh[2 * HH + j]));
    float hold = hin[b * HH + j];
    float h2 = (1.f - z) * n + z * hold;
    hout[b * HH + j] = h2;
    split_store(h2, &g_ah[b * H3 + j], &g_al[b * H3 + j]);
}

// ---------------- host launch ----------------
extern "C" void kernel_launch(void* const* d_in, const int* in_sizes, int n_in,
                              void* d_out, int out_size)
{
    const int*   inputs  = (const int*)d_in[0];
    const float* enc_emb = (const float*)d_in[2];
    const float* W_ih_f  = (const float*)d_in[3];
    const float* W_hh_f  = (const float*)d_in[4];
    const float* b_ih_f  = (const float*)d_in[5];
    const float* b_hh_f  = (const float*)d_in[6];
    const float* W_ih_b  = (const float*)d_in[7];
    const float* W_hh_b  = (const float*)d_in[8];
    const float* b_ih_b  = (const float*)d_in[9];
    const float* b_hh_b  = (const float*)d_in[10];
    const float* W_init  = (const float*)d_in[11];
    const float* b_init  = (const float*)d_in[12];
    const float* dec_emb = (const float*)d_in[13];
    const float* W_ih_d  = (const float*)d_in[14];
    const float* W_hh_d  = (const float*)d_in[15];
    const float* b_ih_d  = (const float*)d_in[16];
    const float* b_hh_d  = (const float*)d_in[17];
    const float* W_lsm   = (const float*)d_in[18];
    const float* b_lsm   = (const float*)d_in[19];
    const float* W_a1    = (const float*)d_in[20];
    const float* b_a1    = (const float*)d_in[21];
    const float* W_a2    = (const float*)d_in[22];
    const float* b_a2    = (const float*)d_in[23];
    float* out = (float*)d_out;

    static float* p_P    = nullptr;
    static float* p_gi_f = nullptr;
    static float* p_gi_b = nullptr;
    static float* p_enc  = nullptr;
    static float* p_hd   = nullptr;
    static float* p_henc = nullptr;
    static float* p_q    = nullptr;
    static cudaStream_t s2 = nullptr;
    static cudaEvent_t ev_root, ev_w;
    if (!p_gi_f) {
        cudaGetSymbolAddress((void**)&p_gi_f, g_gi_f);
        cudaGetSymbolAddress((void**)&p_gi_b, g_gi_b);
        cudaGetSymbolAddress((void**)&p_enc,  g_enc);
        cudaGetSymbolAddress((void**)&p_P,    g_P);
        cudaGetSymbolAddress((void**)&p_hd,   g_hd);
        cudaGetSymbolAddress((void**)&p_henc, g_henc);
        cudaGetSymbolAddress((void**)&p_q,    g_q);
        cudaFuncSetAttribute(logits_mma_kernel,
                             cudaFuncAttributeMaxDynamicSharedMemorySize, LG_SMEM_TOTAL);
        cudaFuncSetAttribute(enc_persist_kernel,
                             cudaFuncAttributeMaxDynamicSharedMemorySize, ENC_SMEM);
        cudaStreamCreateWithFlags(&s2, cudaStreamNonBlocking);
        cudaEventCreateWithFlags(&ev_root, cudaEventDisableTiming);
        cudaEventCreateWithFlags(&ev_w,    cudaEventDisableTiming);
    }

    // fork stream 2 ONCE: W split conversion overlaps encoder phase
    cudaEventRecord(ev_root, 0);
    cudaStreamWaitEvent(s2, ev_root, 0);
    convw_kernel<<<(int)(((size_t)KY * H3 / 4) / 256), 256, 0, s2>>>(W_lsm);
    cudaEventRecord(ev_w, s2);

    init_kernel<<<128, 256>>>();

    sgemm_kernel<<<dim3(H3 / 128, TX * BB / 64), 256>>>(
        enc_emb, inputs, W_ih_f, EE, b_ih_f, p_gi_f, H3, EE);
    sgemm_kernel<<<dim3(H3 / 128, TX * BB / 64), 256>>>(
        enc_emb, inputs, W_ih_b, EE, b_ih_b, p_gi_b, H3, EE);

    enc_persist_kernel<<<dim3(64, 2), 512, ENC_SMEM>>>(W_hh_f, b_hh_f, W_hh_b, b_hh_b);

    sgemm_kernel<<<dim3(HH / 128, TX * BB / 64), 256>>>(
        p_enc, nullptr, W_a1 + HH, H3, b_a1, p_P, HH, CTXD);

    colproj_kernel<<<64, 512>>>(p_henc + 2 * BB * HH, W_init, HH, b_init, p_hd, 1);

    cudaStreamWaitEvent(0, ev_w, 0);

    for (int s = 0; s < TY; s++) {
        float* hcur = p_hd + (s & 1) * BB * HH;
        colproj_kernel<<<64, 512>>>(hcur, W_a1, H3, nullptr, p_q, 0);
        attn_kernel<<<64, 256>>>(W_a2, b_a2, dec_emb);
        decgru_kernel<<<128, 256>>>(s, W_ih_d, W_hh_d, b_ih_d, b_hh_d);
        logits_mma_kernel<<<NTILE, 256, LG_SMEM_TOTAL>>>(b_lsm, out, s);
        lsm_norm_kernel<<<BB * KY / 4 / 256, 256>>>(out, s);
    }
}

// round 7
// speedup vs baseline: 1.1315x; 1.1315x over previous
#include <cuda_runtime.h>
#include <cuda_bf16.h>
#include <math.h>
#include <stdint.h>

// Problem constants
#define TX 64
#define BB 64
#define TY 32
#define EE 256
#define HH 512
#define H3 1536
#define KY 32000
#define CTXD 1024      // 2H
#define RNNIN 1280     // E + 2H
#define NTILE (KY / 256)   // 125 vocab tiles

// ---------------- device scratch ----------------
__device__ float g_gi_f[TX * BB * H3];
__device__ float g_gi_b[TX * BB * H3];
__device__ float g_henc[2][2][BB * HH];
__device__ float g_enc[TX * BB * CTXD];
__device__ float g_P[TX * BB * HH];
__device__ float g_hd[2][BB * HH];
__device__ float g_q[BB * HH];
__device__ float g_rnnin[BB * RNNIN];
__device__ int   g_tok[BB];
__device__ float g_lse[TY * BB];

__device__ __nv_bfloat16 g_wh[(size_t)KY * H3];
__device__ __nv_bfloat16 g_wl[(size_t)KY * H3];
__device__ __nv_bfloat16 g_ah[BB * H3];
__device__ __nv_bfloat16 g_al[BB * H3];

__device__ float g_pm[NTILE][BB];
__device__ int   g_pa[NTILE][BB];
__device__ float g_ps[NTILE][BB];

__device__ volatile unsigned g_bar_gen[2];
__device__ unsigned g_bar_cnt[2];

__device__ __forceinline__ float sigm(float x) { return 1.0f / (1.0f + expf(-x)); }

__device__ __forceinline__ void split_store(float v, __nv_bfloat16* ph, __nv_bfloat16* pl)
{
    __nv_bfloat16 h = __float2bfloat16(v);
    *ph = h;
    *pl = __float2bfloat16(v - __bfloat162float(h));
}

// ---------------- init ----------------
__global__ void init_kernel() {
    int i = blockIdx.x * blockDim.x + threadIdx.x;
    if (i < BB * HH) {
        g_henc[0][0][i] = 0.f;
        g_henc[1][0][i] = 0.f;
    }
    if (i < BB) g_tok[i] = 1;
    if (i < 2) { g_bar_gen[i] = 0; g_bar_cnt[i] = 0; }
}

// ---------------- W_lsm -> bf16 hi/lo split ----------------
__global__ __launch_bounds__(256) void convw_kernel(const float* __restrict__ W) {
    size_t i = (size_t)blockIdx.x * blockDim.x + threadIdx.x;
    const float4* W4 = (const float4*)W;
    float4 v = W4[i];
    __nv_bfloat16 h0 = __float2bfloat16(v.x);
    __nv_bfloat16 h1 = __float2bfloat16(v.y);
    __nv_bfloat16 h2 = __float2bfloat16(v.z);
    __nv_bfloat16 h3 = __float2bfloat16(v.w);
    __nv_bfloat16 l0 = __float2bfloat16(v.x - __bfloat162float(h0));
    __nv_bfloat16 l1 = __float2bfloat16(v.y - __bfloat162float(h1));
    __nv_bfloat16 l2 = __float2bfloat16(v.z - __bfloat162float(h2));
    __nv_bfloat16 l3 = __float2bfloat16(v.w - __bfloat162float(h3));
    __nv_bfloat162* H2 = reinterpret_cast<__nv_bfloat162*>(g_wh);
    __nv_bfloat162* L2 = reinterpret_cast<__nv_bfloat162*>(g_wl);
    H2[2 * i]     = __nv_bfloat162{h0, h1};
    H2[2 * i + 1] = __nv_bfloat162{h2, h3};
    L2[2 * i]     = __nv_bfloat162{l0, l1};
    L2[2 * i + 1] = __nv_bfloat162{l2, l3};
}

// ---------------- mma.sync bf16 helper ----------------
__device__ __forceinline__ void mma16816(float* d, const uint32_t* a, uint32_t b0, uint32_t b1)
{
    asm volatile(
        "mma.sync.aligned.m16n8k16.row.col.f32.bf16.bf16.f32 "
        "{%0,%1,%2,%3}, {%4,%5,%6,%7}, {%8,%9}, {%0,%1,%2,%3};"
        : "+f"(d[0]), "+f"(d[1]), "+f"(d[2]), "+f"(d[3])
        : "r"(a[0]), "r"(a[1]), "r"(a[2]), "r"(a[3]), "r"(b0), "r"(b1));
}

// ---------------- logits GEMM (split bf16, fp32 accum) + per-tile partials ----------------
// 512 threads = 16 warps, each warp M=16 rows. Same tiles/smem as round-4.
#define LG_KC 64
#define LG_ROWB 144
#define LG_W_BYTES (256 * LG_ROWB)
#define LG_A_BYTES (64 * LG_ROWB)
#define LG_STAGE (2 * LG_W_BYTES + 2 * LG_A_BYTES)   // 92160
#define LG_SMEM_TOTAL (2 * LG_STAGE)                 // 184320

__global__ __launch_bounds__(512, 1) void logits_mma_kernel(
    const float* __restrict__ b_lsm, float* __restrict__ out, int step)
{
    extern __shared__ char smem[];
    int tid = threadIdx.x;
    int wid = tid >> 5, lane = tid & 31;
    int vb = blockIdx.x * 256;

    auto load_chunk = [&](int kc, int buf) {
        char* base = smem + buf * LG_STAGE;
        {
            char* dsth = base;
            char* dstl = base + LG_W_BYTES;
            const __nv_bfloat16* sh = g_wh + (size_t)vb * H3 + kc * LG_KC;
            const __nv_bfloat16* sl = g_wl + (size_t)vb * H3 + kc * LG_KC;
#pragma unroll
            for (int it = 0; it < 4; it++) {
                int idx = tid + it * 512;
                int r = idx >> 3, c = idx & 7;
                size_t gofs = (size_t)r * H3 + c * 8;
                uint32_t so = (uint32_t)(r * LG_ROWB + c * 16);
                uint32_t d1 = (uint32_t)__cvta_generic_to_shared(dsth + so);
                uint32_t d2 = (uint32_t)__cvta_generic_to_shared(dstl + so);
                asm volatile("cp.async.cg.shared.global [%0], [%1], 16;" :: "r"(d1), "l"(sh + gofs));
                asm volatile("cp.async.cg.shared.global [%0], [%1], 16;" :: "r"(d2), "l"(sl + gofs));
            }
        }
        {
            char* dsth = base + 2 * LG_W_BYTES;
            char* dstl = dsth + LG_A_BYTES;
            const __nv_bfloat16* sh = g_ah + kc * LG_KC;
            const __nv_bfloat16* sl = g_al + kc * LG_KC;
            int idx = tid;
            int r = idx >> 3, c = idx & 7;
            size_t gofs = (size_t)r * H3 + c * 8;
            uint32_t so = (uint32_t)(r * LG_ROWB + c * 16);
            uint32_t d1 = (uint32_t)__cvta_generic_to_shared(dsth + so);
            uint32_t d2 = (uint32_t)__cvta_generic_to_shared(dstl + so);
            asm volatile("cp.async.cg.shared.global [%0], [%1], 16;" :: "r"(d1), "l"(sh + gofs));
            asm volatile("cp.async.cg.shared.global [%0], [%1], 16;" :: "r"(d2), "l"(sl + gofs));
        }
        asm volatile("cp.async.commit_group;" ::: "memory");
    };

    float acc[8][4];
#pragma unroll
    for (int nt = 0; nt < 8; nt++)
#pragma unroll
        for (int i = 0; i < 4; i++) acc[nt][i] = 0.f;

    int m0 = wid * 16;
    int krow = lane >> 2;
    int kcol4 = (lane & 3) * 4;

    load_chunk(0, 0);

    for (int c = 0; c < H3 / LG_KC; c++) {
        if (c + 1 < H3 / LG_KC) {
            load_chunk(c + 1, (c + 1) & 1);
            asm volatile("cp.async.wait_group 1;" ::: "memory");
        } else {
            asm volatile("cp.async.wait_group 0;" ::: "memory");
        }
        __syncthreads();

        char* base = smem + (c & 1) * LG_STAGE;
        const char* wh = base;
        const char* wl = base + LG_W_BYTES;
        const char* ab_h = base + 2 * LG_W_BYTES;
        const char* ab_l = ab_h + LG_A_BYTES;

#pragma unroll
        for (int kt = 0; kt < 4; kt++) {
            int kb = kt * 32 + kcol4;
            uint32_t ah[4], al[4];
            int ro = (m0 + krow) * LG_ROWB + kb;
            ah[0] = *(const uint32_t*)(wh + ro);
            ah[1] = *(const uint32_t*)(wh + ro + 8 * LG_ROWB);
            ah[2] = *(const uint32_t*)(wh + ro + 16);
            ah[3] = *(const uint32_t*)(wh + ro + 8 * LG_ROWB + 16);
            al[0] = *(const uint32_t*)(wl + ro);
            al[1] = *(const uint32_t*)(wl + ro + 8 * LG_ROWB);
            al[2] = *(const uint32_t*)(wl + ro + 16);
            al[3] = *(const uint32_t*)(wl + ro + 8 * LG_ROWB + 16);
#pragma unroll
            for (int nt = 0; nt < 8; nt++) {
                int rb = (nt * 8 + krow) * LG_ROWB + kb;
                uint32_t bh0 = *(const uint32_t*)(ab_h + rb);
                uint32_t bh1 = *(const uint32_t*)(ab_h + rb + 16);
                uint32_t bl0 = *(const uint32_t*)(ab_l + rb);
                uint32_t bl1 = *(const uint32_t*)(ab_l + rb + 16);
                mma16816(acc[nt], ah, bh0, bh1);
                mma16816(acc[nt], ah, bl0, bl1);
                mma16816(acc[nt], al, bh0, bh1);
            }
        }
        __syncthreads();
    }

    // ---- epilogue: bias + store ----
    float* obase = out + (size_t)step * BB * KY;
#pragma unroll
    for (int h = 0; h < 2; h++) {
        int v = vb + m0 + krow + h * 8;
        float bias = b_lsm[v];
#pragma unroll
        for (int nt = 0; nt < 8; nt++) {
            int b0 = nt * 8 + (lane & 3) * 2;
            acc[nt][h * 2 + 0] += bias;
            acc[nt][h * 2 + 1] += bias;
            obase[(size_t)b0 * KY + v]       = acc[nt][h * 2 + 0];
            obase[(size_t)(b0 + 1) * KY + v] = acc[nt][h * 2 + 1];
        }
    }
    __syncthreads();  // pipeline buffers done; reuse smem

    float* smf  = (float*)smem;             // [16][64]
    int*   smi  = (int*)(smem + 4096);      // [16][64]
    float* tmx  = (float*)(smem + 8192);    // [64]
    int*   targ = (int*)(smem + 8448);      // [64]

    int vbase = vb + m0 + krow;
    // phase 1: max + argmax
#pragma unroll
    for (int nt = 0; nt < 8; nt++) {
#pragma unroll
        for (int c = 0; c < 2; c++) {
            int bcol = nt * 8 + (lane & 3) * 2 + c;
            float mv = acc[nt][c];     int mi = vbase;
            float v2 = acc[nt][2 + c];
            if (v2 > mv) { mv = v2; mi = vbase + 8; }
#pragma unroll
            for (int o = 4; o <= 16; o <<= 1) {
                float ov = __shfl_xor_sync(0xffffffffu, mv, o);
                int oi = __shfl_xor_sync(0xffffffffu, mi, o);
                if (ov > mv || (ov == mv && oi < mi)) { mv = ov; mi = oi; }
            }
            if ((lane >> 2) == 0) { smf[wid * 64 + bcol] = mv; smi[wid * 64 + bcol] = mi; }
        }
    }
    __syncthreads();
    if (tid < 64) {
        float mv = smf[tid]; int mi = smi[tid];
#pragma unroll
        for (int w = 1; w < 16; w++) {
            float ov = smf[w * 64 + tid]; int oi = smi[w * 64 + tid];
            if (ov > mv || (ov == mv && oi < mi)) { mv = ov; mi = oi; }
        }
        tmx[tid] = mv; targ[tid] = mi;
    }
    __syncthreads();
    // phase 2: sum of exp(x - tile_max)
#pragma unroll
    for (int nt = 0; nt < 8; nt++) {
#pragma unroll
        for (int c = 0; c < 2; c++) {
            int bcol = nt * 8 + (lane & 3) * 2 + c;
            float tm = tmx[bcol];
            float s = expf(acc[nt][c] - tm) + expf(acc[nt][2 + c] - tm);
#pragma unroll
            for (int o = 4; o <= 16; o <<= 1)
                s += __shfl_xor_sync(0xffffffffu, s, o);
            if ((lane >> 2) == 0) smf[wid * 64 + bcol] = s;
        }
    }
    __syncthreads();
    if (tid < 64) {
        float s = 0.f;
#pragma unroll
        for (int w = 0; w < 16; w++) s += smf[w * 64 + tid];
        g_pm[blockIdx.x][tid] = tmx[tid];
        g_pa[blockIdx.x][tid] = targ[tid];
        g_ps[blockIdx.x][tid] = s;
    }
}

// ---------------- log-softmax finalize: merge tile partials + normalize ----------------
// grid (64 b, 4 segs), 256 threads
__global__ __launch_bounds__(256) void lsm_kernel(float* __restrict__ out, int step)
{
    __shared__ float sm[128];
    __shared__ int   si[128];
    __shared__ float ssum[128];

    int b = blockIdx.x;
    int seg = blockIdx.y;
    int tid = threadIdx.x;

    float m = -1e30f; int a = 0x7fffffff;
    if (tid < NTILE) { m = g_pm[tid][b]; a = g_pa[tid][b]; }
    if (tid < 128) { sm[tid] = m; si[tid] = a; }
    __syncthreads();
    for (int o = 64; o > 0; o >>= 1) {
        if (tid < o) {
            float ov = sm[tid + o]; int oi = si[tid + o];
            if (ov > sm[tid] || (ov == sm[tid] && oi < si[tid])) { sm[tid] = ov; si[tid] = oi; }
        }
        __syncthreads();
    }
    float M = sm[0];

    float s = 0.f;
    if (tid < NTILE) s = g_ps[tid][b] * expf(g_pm[tid][b] - M);
    if (tid < 128) ssum[tid] = s;
    __syncthreads();
    for (int o = 64; o > 0; o >>= 1) {
        if (tid < o) ssum[tid] += ssum[tid + o];
        __syncthreads();
    }
    float lse = M + logf(ssum[0]);

    if (seg == 0 && tid == 0) g_tok[b] = si[0];

    float* row = out + (size_t)(step * BB + b) * KY;
    int i0 = seg * (KY / 4);
    for (int i = i0 + tid; i < i0 + KY / 4; i += 256)
        row[i] -= lse;
}

// ---------------- generic SGEMM ----------------
__global__ __launch_bounds__(256) void sgemm_kernel(
    const float* __restrict__ A, const int* __restrict__ gather,
    const float* __restrict__ W, int ldw,
    const float* __restrict__ bias,
    float* __restrict__ C, int N, int K)
{
    __shared__ float As[16][64];
    __shared__ float Ws[16][128];
    int tid = threadIdx.x;
    int m0 = blockIdx.y * 64;
    int n0 = blockIdx.x * 128;
    int tx = tid & 15, ty = tid >> 4;

    float acc[4][8];
#pragma unroll
    for (int i = 0; i < 4; i++)
#pragma unroll
        for (int j = 0; j < 8; j++) acc[i][j] = 0.f;

    int lrow = tid >> 2;
    int lk = (tid & 3) * 4;
    int arow = m0 + lrow;
    int aphys = gather ? gather[arow] : arow;
    const float* Aptr = A + (size_t)aphys * K + lk;

    for (int k0 = 0; k0 < K; k0 += 16) {
        float4 av = *(const float4*)(Aptr + k0);
        As[lk + 0][lrow] = av.x; As[lk + 1][lrow] = av.y;
        As[lk + 2][lrow] = av.z; As[lk + 3][lrow] = av.w;
#pragma unroll
        for (int r = 0; r < 2; r++) {
            int nrow = lrow + r * 64;
            float4 wv = *(const float4*)(W + (size_t)(n0 + nrow) * ldw + k0 + lk);
            Ws[lk + 0][nrow] = wv.x; Ws[lk + 1][nrow] = wv.y;
            Ws[lk + 2][nrow] = wv.z; Ws[lk + 3][nrow] = wv.w;
        }
        __syncthreads();
#pragma unroll
        for (int kk = 0; kk < 16; kk++) {
            float a[4];
#pragma unroll
            for (int i = 0; i < 4; i++) a[i] = As[kk][ty * 4 + i];
            float4 b0 = *(const float4*)&Ws[kk][tx * 8];
            float4 b1 = *(const float4*)&Ws[kk][tx * 8 + 4];
            float bb8[8] = { b0.x, b0.y, b0.z, b0.w, b1.x, b1.y, b1.z, b1.w };
#pragma unroll
            for (int i = 0; i < 4; i++)
#pragma unroll
                for (int j = 0; j < 8; j++) acc[i][j] += a[i] * bb8[j];
        }
        __syncthreads();
    }
#pragma unroll
    for (int i = 0; i < 4; i++) {
        int m = m0 + ty * 4 + i;
        float* crow = C + (size_t)m * N + n0 + tx * 8;
#pragma unroll
        for (int j = 0; j < 8; j++) {
            float v = acc[i][j];
            if (bias) v += bias[n0 + tx * 8 + j];
            crow[j] = v;
        }
    }
}

// ---------------- persistent encoder ----------------
#define ENC_WS_FLOATS (24 * 512)
#define ENC_SMEM ((ENC_WS_FLOATS + 128 * 65) * 4)

__device__ __forceinline__ void dir_barrier(int dir, int tid)
{
    __threadfence();
    __syncthreads();
    if (tid == 0) {
        unsigned gen = g_bar_gen[dir];
        unsigned t = atomicAdd(&g_bar_cnt[dir], 1u);
        if (t == 63u) {
            g_bar_cnt[dir] = 0u;
            __threadfence();
            g_bar_gen[dir] = gen + 1u;
        } else {
            while (g_bar_gen[dir] == gen) __nanosleep(40);
        }
    }
    __syncthreads();
}

__global__ __launch_bounds__(512, 1) void enc_persist_kernel(
    const float* __restrict__ Whh_f, const float* __restrict__ bhh_f,
    const float* __restrict__ Whh_b, const float* __restrict__ bhh_b)
{
    extern __shared__ float sm[];
    float* ws = sm;
    float (*hs)[65] = (float(*)[65])(sm + ENC_WS_FLOATS);

    int dir = blockIdx.y;
    const float* Whh = dir ? Whh_b : Whh_f;
    const float* bhh = dir ? bhh_b : bhh_f;
    int tid = threadIdx.x;
    int b = tid & 63;
    int jl = tid >> 6;
    int j0 = blockIdx.x * 8;
    int j = j0 + jl;
    int colofs = dir ? HH : 0;

    for (int idx = tid; idx < ENC_WS_FLOATS; idx += 512) {
        int rr = idx >> 9, kk = idx & 511;
        ws[idx] = Whh[(size_t)((rr >> 3) * HH + j0 + (rr & 7)) * HH + kk];
    }
    float br = bhh[j], bz = bhh[HH + j], bn = bhh[2 * HH + j];
    __syncthreads();

    for (int t = 0; t < TX; t++) {
        int par = t & 1;
        int row = dir ? (TX - 1 - t) : t;
        const float* gi = (dir ? g_gi_b : g_gi_f) + (size_t)row * BB * H3;
        const float* hin = g_henc[dir][par];
        float* hout = g_henc[dir][par ^ 1];

        float dr = 0.f, dz = 0.f, dn = 0.f;
        for (int kb = 0; kb < 4; kb++) {
            int kbase = kb * 128;
#pragma unroll
            for (int r = 0; r < 16; r++) {
                int i = tid + r * 512;
                int kk = i & 127, bb2 = i >> 7;
                hs[kk][bb2] = __ldcg(&hin[bb2 * HH + kbase + kk]);
            }
            __syncthreads();
            const float* wr4 = ws + jl * 512 + kbase;
            const float* wz4 = ws + (8 + jl) * 512 + kbase;
            const float* wn4 = ws + (16 + jl) * 512 + kbase;
#pragma unroll 8
            for (int k = 0; k < 128; k += 4) {
                float4 wr = *(const float4*)(wr4 + k);
                float4 wz = *(const float4*)(wz4 + k);
                float4 wn = *(const float4*)(wn4 + k);
                float h0 = hs[k][b], h1 = hs[k + 1][b], h2v = hs[k + 2][b], h3v = hs[k + 3][b];
                dr += h0 * wr.x + h1 * wr.y + h2v * wr.z + h3v * wr.w;
                dz += h0 * wz.x + h1 * wz.y + h2v * wz.z + h3v * wz.w;
                dn += h0 * wn.x + h1 * wn.y + h2v * wn.z + h3v * wn.w;
            }
            __syncthreads();
        }

        const float* girow = gi + b * H3;
        float r = sigm(girow[j] + dr + br);
        float z = sigm(girow[HH + j] + dz + bz);
        float n = tanhf(girow[2 * HH + j] + r * (dn + bn));
        float hold = __ldcg(&hin[b * HH + j]);
        float h2 = (1.f - z) * n + z * hold;
        __stcg(&hout[b * HH + j], h2);
        g_enc[(size_t)(row * BB + b) * CTXD + colofs + j] = h2;

        if (t + 1 < TX) dir_barrier(dir, tid);
    }
}

// ---------------- column projection ----------------
__global__ __launch_bounds__(512) void colproj_kernel(
    const float* __restrict__ src, const float* __restrict__ W, int ldw,
    const float* __restrict__ bias, float* __restrict__ dst, int act)
{
    __shared__ float hs[128][65];
    __shared__ float ws[8][128];
    int tid = threadIdx.x;
    int b = tid & 63;
    int jl = tid >> 6;
    int j0 = blockIdx.x * 8;
    int j = j0 + jl;

    float acc = 0.f;
    for (int kb = 0; kb < 4; kb++) {
        int kbase = kb * 128;
#pragma unroll
        for (int r = 0; r < 16; r++) {
            int i = tid + r * 512;
            int kk = i & 127, bb2 = i >> 7;
            hs[kk][bb2] = src[bb2 * HH + kbase + kk];
        }
#pragma unroll
        for (int r = 0; r < 2; r++) {
            int i = tid + r * 512;
            int kk = i & 127, rr = i >> 7;
            ws[rr][kk] = W[(size_t)(j0 + rr) * ldw + kbase + kk];
        }
        __syncthreads();
#pragma unroll 8
        for (int k = 0; k < 128; k += 4) {
            float4 wv = *(const float4*)&ws[jl][k];
            acc += hs[k][b] * wv.x + hs[k + 1][b] * wv.y
                 + hs[k + 2][b] * wv.z + hs[k + 3][b] * wv.w;
        }
        __syncthreads();
    }
    if (bias) acc += bias[j];
    if (act) acc = tanhf(acc);
    dst[b * HH + j] = acc;
}

// ---------------- attention + embedding (fused) ----------------
__global__ __launch_bounds__(256) void attn_kernel(
    const float* __restrict__ W_a2, const float* __restrict__ b_a2,
    const float* __restrict__ dec_emb)
{
    __shared__ float qs[HH];
    __shared__ float was[HH];
    __shared__ float ss[TX];
    __shared__ float wgt[TX];

    int b = blockIdx.x;
    int tid = threadIdx.x;
    int lane = tid & 31;
    int warp = tid >> 5;

    int tok = g_tok[b];
    for (int i = tid; i < EE; i += 256)
        g_rnnin[b * RNNIN + i] = dec_emb[(size_t)tok * EE + i];

    for (int i = tid; i < HH; i += 256) {
        qs[i] = g_q[b * HH + i];
        was[i] = W_a2[i];
    }
    __syncthreads();

    for (int tt = 0; tt < 8; tt++) {
        int t = warp * 8 + tt;
        const float* Prow = g_P + (size_t)(t * BB + b) * HH;
        float p = 0.f;
#pragma unroll 4
        for (int jj = lane; jj < HH; jj += 32)
            p += was[jj] * tanhf(qs[jj] + Prow[jj]);
#pragma unroll
        for (int o = 16; o > 0; o >>= 1)
            p += __shfl_down_sync(0xffffffffu, p, o);
        if (lane == 0) ss[t] = p + b_a2[0];
    }
    __syncthreads();

    if (tid < 32) {
        float v0 = ss[tid], v1 = ss[tid + 32];
        float m = fmaxf(v0, v1);
#pragma unroll
        for (int o = 16; o > 0; o >>= 1)
            m = fmaxf(m, __shfl_xor_sync(0xffffffffu, m, o));
        float e0 = expf(v0 - m), e1 = expf(v1 - m);
        float s = e0 + e1;
#pragma unroll
        for (int o = 16; o > 0; o >>= 1)
            s += __shfl_xor_sync(0xffffffffu, s, o);
        wgt[tid] = e0 / s;
        wgt[tid + 32] = e1 / s;
    }
    __syncthreads();

    for (int i = tid; i < CTXD; i += 256) {
        float c = 0.f;
#pragma unroll 8
        for (int t = 0; t < TX; t++)
            c += wgt[t] * g_enc[(size_t)(t * BB + b) * CTXD + i];
        g_rnnin[b * RNNIN + EE + i] = c;
        split_store(c, &g_ah[b * H3 + HH + i], &g_al[b * H3 + HH + i]);
    }
}

// ---------------- decoder GRU ----------------
__global__ __launch_bounds__(256) void decgru_kernel(
    int s,
    const float* __restrict__ Wih, const float* __restrict__ Whh,
    const float* __restrict__ bih, const float* __restrict__ bhh)
{
    __shared__ float xs[128][65];
    __shared__ float ws[12][128];

    int tid = threadIdx.x;
    int b = tid & 63;
    int jl = tid >> 6;
    int j0 = blockIdx.x * 4;
    int j = j0 + jl;
    int par = s & 1;
    const float* hin = g_hd[par];
    float* hout = g_hd[par ^ 1];

    float ar = 0.f, az = 0.f, anx = 0.f, anh = 0.f;

    for (int kb = 0; kb < 10; kb++) {
        int kbase = kb * 128;
#pragma unroll
        for (int r = 0; r < 32; r++) {
            int i = tid + r * 256;
            int kk = i & 127, bb2 = i >> 7;
            xs[kk][bb2] = g_rnnin[bb2 * RNNIN + kbase + kk];
        }
#pragma unroll
        for (int r = 0; r < 6; r++) {
            int i = tid + r * 256;
            int kk = i & 127, rr = i >> 7;
            int g = rr >> 2, jloc = rr & 3;
            ws[rr][kk] = Wih[(size_t)(g * HH + j0 + jloc) * RNNIN + kbase + kk];
        }
        __syncthreads();
#pragma unroll 8
        for (int k = 0; k < 128; k += 4) {
            float4 wr = *(const float4*)&ws[jl][k];
            float4 wz = *(const float4*)&ws[4 + jl][k];
            float4 wn = *(const float4*)&ws[8 + jl][k];
            float x0 = xs[k][b], x1 = xs[k + 1][b], x2 = xs[k + 2][b], x3 = xs[k + 3][b];
            ar += x0 * wr.x + x1 * wr.y + x2 * wr.z + x3 * wr.w;
            az += x0 * wz.x + x1 * wz.y + x2 * wz.z + x3 * wz.w;
            anx += x0 * wn.x + x1 * wn.y + x2 * wn.z + x3 * wn.w;
        }
        __syncthreads();
    }

    for (int kb = 0; kb < 4; kb++) {
        int kbase = kb * 128;
#pragma unroll
        for (int r = 0; r < 32; r++) {
            int i = tid + r * 256;
            int kk = i & 127, bb2 = i >> 7;
            xs[kk][bb2] = hin[bb2 * HH + kbase + kk];
        }
#pragma unroll
        for (int r = 0; r < 6; r++) {
            int i = tid + r * 256;
            int kk = i & 127, rr = i >> 7;
            int g = rr >> 2, jloc = rr & 3;
            ws[rr][kk] = Whh[(size_t)(g * HH + j0 + jloc) * HH + kbase + kk];
        }
        __syncthreads();
#pragma unroll 8
        for (int k = 0; k < 128; k += 4) {
            float4 wr = *(const float4*)&ws[jl][k];
            float4 wz = *(const float4*)&ws[4 + jl][k];
            float4 wn = *(const float4*)&ws[8 + jl][k];
            float x0 = xs[k][b], x1 = xs[k + 1][b], x2 = xs[k + 2][b], x3 = xs[k + 3][b];
            ar += x0 * wr.x + x1 * wr.y + x2 * wr.z + x3 * wr.w;
            az += x0 * wz.x + x1 * wz.y + x2 * wz.z + x3 * wz.w;
            anh += x0 * wn.x + x1 * wn.y + x2 * wn.z + x3 * wn.w;
        }
        __syncthreads();
    }

    float r = sigm(ar + bih[j] + bhh[j]);
    float z = sigm(az + bih[HH + j] + bhh[HH + j]);
    float n = tanhf(anx + bih[2 * HH + j] + r * (anh + bhh[2 * HH + j]));
    float hold = hin[b * HH + j];
    float h2 = (1.f - z) * n + z * hold;
    hout[b * HH + j] = h2;
    split_store(h2, &g_ah[b * H3 + j], &g_al[b * H3 + j]);
}

// ---------------- host launch ----------------
extern "C" void kernel_launch(void* const* d_in, const int* in_sizes, int n_in,
                              void* d_out, int out_size)
{
    const int*   inputs  = (const int*)d_in[0];
    const float* enc_emb = (const float*)d_in[2];
    const float* W_ih_f  = (const float*)d_in[3];
    const float* W_hh_f  = (const float*)d_in[4];
    const float* b_ih_f  = (const float*)d_in[5];
    const float* b_hh_f  = (const float*)d_in[6];
    const float* W_ih_b  = (const float*)d_in[7];
    const float* W_hh_b  = (const float*)d_in[8];
    const float* b_ih_b  = (const float*)d_in[9];
    const float* b_hh_b  = (const float*)d_in[10];
    const float* W_init  = (const float*)d_in[11];
    const float* b_init  = (const float*)d_in[12];
    const float* dec_emb = (const float*)d_in[13];
    const float* W_ih_d  = (const float*)d_in[14];
    const float* W_hh_d  = (const float*)d_in[15];
    const float* b_ih_d  = (const float*)d_in[16];
    const float* b_hh_d  = (const float*)d_in[17];
    const float* W_lsm   = (const float*)d_in[18];
    const float* b_lsm   = (const float*)d_in[19];
    const float* W_a1    = (const float*)d_in[20];
    const float* b_a1    = (const float*)d_in[21];
    const float* W_a2    = (const float*)d_in[22];
    const float* b_a2    = (const float*)d_in[23];
    float* out = (float*)d_out;

    static float* p_P    = nullptr;
    static float* p_gi_f = nullptr;
    static float* p_gi_b = nullptr;
    static float* p_enc  = nullptr;
    static float* p_hd   = nullptr;
    static float* p_henc = nullptr;
    static float* p_q    = nullptr;
    static cudaStream_t s2 = nullptr;
    static cudaEvent_t ev_root, ev_w;
    if (!p_gi_f) {
        cudaGetSymbolAddress((void**)&p_gi_f, g_gi_f);
        cudaGetSymbolAddress((void**)&p_gi_b, g_gi_b);
        cudaGetSymbolAddress((void**)&p_enc,  g_enc);
        cudaGetSymbolAddress((void**)&p_P,    g_P);
        cudaGetSymbolAddress((void**)&p_hd,   g_hd);
        cudaGetSymbolAddress((void**)&p_henc, g_henc);
        cudaGetSymbolAddress((void**)&p_q,    g_q);
        cudaFuncSetAttribute(logits_mma_kernel,
                             cudaFuncAttributeMaxDynamicSharedMemorySize, LG_SMEM_TOTAL);
        cudaFuncSetAttribute(enc_persist_kernel,
                             cudaFuncAttributeMaxDynamicSharedMemorySize, ENC_SMEM);
        cudaStreamCreateWithFlags(&s2, cudaStreamNonBlocking);
        cudaEventCreateWithFlags(&ev_root, cudaEventDisableTiming);
        cudaEventCreateWithFlags(&ev_w,    cudaEventDisableTiming);
    }

    // fork stream 2: W split conversion overlaps encoder phase
    cudaEventRecord(ev_root, 0);
    cudaStreamWaitEvent(s2, ev_root, 0);
    convw_kernel<<<(int)(((size_t)KY * H3 / 4) / 256), 256, 0, s2>>>(W_lsm);
    cudaEventRecord(ev_w, s2);

    init_kernel<<<128, 256>>>();

    sgemm_kernel<<<dim3(H3 / 128, TX * BB / 64), 256>>>(
        enc_emb, inputs, W_ih_f, EE, b_ih_f, p_gi_f, H3, EE);
    sgemm_kernel<<<dim3(H3 / 128, TX * BB / 64), 256>>>(
        enc_emb, inputs, W_ih_b, EE, b_ih_b, p_gi_b, H3, EE);

    enc_persist_kernel<<<dim3(64, 2), 512, ENC_SMEM>>>(W_hh_f, b_hh_f, W_hh_b, b_hh_b);

    sgemm_kernel<<<dim3(HH / 128, TX * BB / 64), 256>>>(
        p_enc, nullptr, W_a1 + HH, H3, b_a1, p_P, HH, CTXD);

    colproj_kernel<<<64, 512>>>(p_henc + 2 * BB * HH, W_init, HH, b_init, p_hd, 1);

    cudaStreamWaitEvent(0, ev_w, 0);

    for (int s = 0; s < TY; s++) {
        float* hcur = p_hd + (s & 1) * BB * HH;
        colproj_kernel<<<64, 512>>>(hcur, W_a1, H3, nullptr, p_q, 0);
        attn_kernel<<<64, 256>>>(W_a2, b_a2, dec_emb);
        decgru_kernel<<<128, 256>>>(s, W_ih_d, W_hh_d, b_ih_d, b_hh_d);
        logits_mma_kernel<<<NTILE, 512, LG_SMEM_TOTAL>>>(b_lsm, out, s);
        lsm_kernel<<<dim3(64, 4), 256>>>(out, s);
    }
}